// round 9
// baseline (speedup 1.0000x reference)
#include <cuda_runtime.h>
#include <stdint.h>
#include <math.h>

// ---------------------------------------------------------------------------
// Problem constants
// ---------------------------------------------------------------------------
#define NUM_CLASSES 10
#define DD     64
#define MAXB   1024
#define NE_PAD 50048           // 391 tiles of 128
#define GAMMA  1.0f
#define EPS    1e-12f

// Tiling: int8 IMMA m16n8k32 filter GEMM
#define TM 128
#define TN 128
#define GCOLS 37               // grid = 8 x 37 = 296 CTAs = 2/SM, one wave
#define ROWB 80                // smem row stride: 64 int8 + 16 pad (conflict-free)

#define QSCALE 16.0f           // int8 quantization scale
#define MAXSURV (1u * 1024u * 1024u)

// ---------------------------------------------------------------------------
// Scratch (__device__ globals; no cudaMalloc allowed)
// ---------------------------------------------------------------------------
__device__ int8_t g_ei8[(size_t)NE_PAD * DD];
__device__ int8_t g_xi8[(size_t)MAXB * DD];
__device__ float g_e2[NE_PAD];          // exact ||e||^2 (for survivor recompute)
__device__ float g_x2[MAXB];
__device__ float g_ce[NE_PAD];          // e2 - L1e/16  (gate term)
__device__ float g_rx[MAXB];            // x2 - L1x/16
__device__ float g_class[MAXB * NUM_CLASSES];
__device__ float g_beta;
__device__ unsigned int g_nsurv;
__device__ unsigned int g_done;
__device__ unsigned int g_surv[MAXSURV];

// ---------------------------------------------------------------------------
// PTX helpers (baseline ISA only: ldmatrix, mma.sync s8, cp.async)
// ---------------------------------------------------------------------------
__device__ __forceinline__ uint32_t smem_to_u32(const void* p) {
    uint32_t a;
    asm("{ .reg .u64 t; cvta.to.shared.u64 t, %1; cvt.u32.u64 %0, t; }"
        : "=r"(a) : "l"(p));
    return a;
}
__device__ __forceinline__ void ldsm_x4(uint32_t* r, uint32_t addr) {
    asm volatile("ldmatrix.sync.aligned.m8n8.x4.shared.b16 {%0,%1,%2,%3}, [%4];"
                 : "=r"(r[0]), "=r"(r[1]), "=r"(r[2]), "=r"(r[3]) : "r"(addr));
}
__device__ __forceinline__ void ldsm_x2(uint32_t* r, uint32_t addr) {
    asm volatile("ldmatrix.sync.aligned.m8n8.x2.shared.b16 {%0,%1}, [%2];"
                 : "=r"(r[0]), "=r"(r[1]) : "r"(addr));
}
// s8 IMMA: m16n8k32. Fragment BYTE layout matches bf16 m16n8k16 exactly, so
// the same ldmatrix addressing applies to 64-byte int8 rows.
__device__ __forceinline__ void mma_s8(int* c, const uint32_t* a,
                                       const uint32_t* b) {
    asm volatile(
        "mma.sync.aligned.m16n8k32.row.col.s32.s8.s8.s32 "
        "{%0,%1,%2,%3}, {%4,%5,%6,%7}, {%8,%9}, {%0,%1,%2,%3};"
        : "+r"(c[0]), "+r"(c[1]), "+r"(c[2]), "+r"(c[3])
        : "r"(a[0]), "r"(a[1]), "r"(a[2]), "r"(a[3]), "r"(b[0]), "r"(b[1]));
}
__device__ __forceinline__ void cp_async16(uint32_t dst, const void* src) {
    asm volatile("cp.async.cg.shared.global [%0], [%1], 16;"
                 :: "r"(dst), "l"(src) : "memory");
}
__device__ __forceinline__ void cp_commit() {
    asm volatile("cp.async.commit_group;" ::: "memory");
}
template <int N>
__device__ __forceinline__ void cp_wait() {
    asm volatile("cp.async.wait_group %0;" :: "n"(N) : "memory");
}

// ---------------------------------------------------------------------------
// Prep: int8 quantization (scale 16), exact L2 norms, gate terms Rx/Ce,
// beta = softplus(beta_raw), zero bins. 8 threads per row, 8 floats each.
// ---------------------------------------------------------------------------
__global__ void prep_kernel(const float* __restrict__ x,
                            const float* __restrict__ ex,
                            const float* __restrict__ beta_raw,
                            int B, int NE) {
    const int t = threadIdx.x;
    const int gid = blockIdx.x * 256 + t;
    if (gid < MAXB * NUM_CLASSES) g_class[gid] = 0.f;
    if (gid == 0) {
        float br = beta_raw[0];
        g_beta = (br > 20.f) ? br : log1pf(expf(br));
        g_nsurv = 0u;
        g_done  = 0u;
    }
    const int R = blockIdx.x * 32 + (t >> 3);   // padded row index
    const int part = t & 7;                      // 8-float segment
    bool is_x = false;
    int outr = R;
    const float* src = nullptr;
    if (R < NE_PAD) {
        if (R < NE) src = ex + (size_t)R * DD + part * 8;
    } else {
        int xr = R - NE_PAD;
        if (xr >= MAXB) return;
        is_x = true; outr = xr;
        if (xr < B) src = x + (size_t)xr * DD + part * 8;
    }
    float v[8];
    float s = 0.f, l1 = 0.f;
    if (src) {
        #pragma unroll
        for (int q = 0; q < 2; q++) {
            float4 f = ((const float4*)src)[q];
            v[4*q+0] = f.x; v[4*q+1] = f.y; v[4*q+2] = f.z; v[4*q+3] = f.w;
            s  += f.x*f.x + f.y*f.y + f.z*f.z + f.w*f.w;
            l1 += fabsf(f.x) + fabsf(f.y) + fabsf(f.z) + fabsf(f.w);
        }
    } else {
        #pragma unroll
        for (int q = 0; q < 8; q++) v[q] = 0.f;
    }
    #pragma unroll
    for (int d = 1; d <= 4; d <<= 1) {
        s  += __shfl_xor_sync(0xFFFFFFFFu, s, d);
        l1 += __shfl_xor_sync(0xFFFFFFFFu, l1, d);
    }
    // quantize: q = round(16*v), clamp to [-127,127]
    alignas(8) int8_t qb[8];
    #pragma unroll
    for (int q = 0; q < 8; q++) {
        int iv = __float2int_rn(v[q] * QSCALE);
        iv = iv > 127 ? 127 : (iv < -127 ? -127 : iv);
        qb[q] = (int8_t)iv;
    }
    int8_t* dst = (is_x ? (g_xi8 + (size_t)outr * DD)
                        : (g_ei8 + (size_t)outr * DD)) + part * 8;
    *(uint2*)dst = *(uint2*)qb;
    if (part == 0) {
        float rterm = s - l1 * (1.0f / QSCALE);   // x2 - L1/16
        if (is_x) {
            g_x2[outr] = (outr < B) ? s : 0.f;
            g_rx[outr] = (outr < B) ? rterm : 3.0e8f;
        } else {
            g_e2[outr] = (outr < NE) ? s : 3.0e8f;
            g_ce[outr] = (outr < NE) ? rterm : 3.0e8f;  // padding never fires
        }
    }
}

// ---------------------------------------------------------------------------
// Main: int8 IMMA filter GEMM, cp.async double-buffered B tiles.
// Hierarchical gate: per column-group integer max (IMNMX tree) -> one
// conservative compare -> rare detailed scan -> global survivor push.
// Guarantee: d2_true >= Rx + Ce - dotq/128 - 0.375, so gating
// Rx + Ce - dotq/128 < 60/beta + 0.5 includes every true survivor.
// ---------------------------------------------------------------------------
__global__ void __launch_bounds__(256, 2)
exemplar_mma_kernel(int B, int NE) {
    __shared__ __align__(16) char sA[TM * ROWB];       // 10240
    __shared__ __align__(16) char sB[2][TN * ROWB];    // 2 x 10240

    const uint32_t saU = smem_to_u32(sA);
    const uint32_t sbU[2] = { smem_to_u32(sB[0]), smem_to_u32(sB[1]) };

    const int t = threadIdx.x;
    const int wid = t >> 5, lane = t & 31;
    const int warpM = wid >> 2;            // 0..1
    const int warpN = wid & 3;             // 0..3
    const int bm = blockIdx.y * TM;
    const int NT = (NE + TN - 1) / TN;

    // Load A tile (128 rows x 64 int8) once.
    for (int i = t; i < TM * 4; i += 256) {
        int r = i >> 2, c = i & 3;
        *(uint4*)(sA + r * ROWB + c * 16) =
            *(const uint4*)(g_xi8 + (size_t)(bm + r) * DD + c * 16);
    }

    // ldmatrix lane-address components (identical byte layout to bf16-k16)
    const int rowA = (lane & 7) + ((lane >> 3) & 1) * 8;
    const int kAby = ((lane >> 4) & 1) * 16;           // byte offset 0/16
    const int l16  = lane & 15;
    const int rowBf = l16 & 7;
    const int kBby  = ((l16 >> 3) & 1) * 16;

    uint32_t aAddr[4];
    #pragma unroll
    for (int mi = 0; mi < 4; mi++)
        aAddr[mi] = saU + (uint32_t)(warpM * 64 + mi * 16 + rowA) * ROWB + kAby;
    uint32_t bOff[4];
    #pragma unroll
    for (int ni = 0; ni < 4; ni++)
        bOff[ni] = (uint32_t)(warpN * 32 + ni * 8 + rowBf) * ROWB + kBby;

    const float beta = g_beta;
    const float thrP = 60.f / beta + 0.5f;   // margin covers quant+fp error
    const float inv128 = 1.0f / 128.0f;

    // Per-thread gate terms for its 8 M-rows; rxmin for the group bound.
    float Rxv[8];
    #pragma unroll
    for (int mi = 0; mi < 4; mi++) {
        int r0 = bm + warpM * 64 + mi * 16 + (lane >> 2);
        Rxv[mi * 2 + 0] = g_rx[r0];
        Rxv[mi * 2 + 1] = g_rx[r0 + 8];
    }
    float rxmin = Rxv[0];
    #pragma unroll
    for (int i = 1; i < 8; i++) rxmin = fminf(rxmin, Rxv[i]);

    // cp.async B-tile issue: 2 x 16B per thread (512 chunks per 8KB tile).
    const int pr = t >> 1;                 // rows 0..127 (2 threads/row)
    const int pc = (t & 1) * 2;            // chunks pc, pc+1
    auto issue_b = [&](uint32_t sbase, int bn) {
        const int8_t* src = g_ei8 + (size_t)(bn + pr) * DD;
        uint32_t drow = sbase + (uint32_t)pr * ROWB;
        cp_async16(drow + (pc + 0) * 16, src + (pc + 0) * 16);
        cp_async16(drow + (pc + 1) * 16, src + (pc + 1) * 16);
    };

    issue_b(sbU[0], blockIdx.x * TN);
    cp_commit();

    int it = 0;
    for (int et = blockIdx.x; et < NT; et += GCOLS, it++) {
        const int bn = et * TN;
        const uint32_t cur = sbU[it & 1];
        const int etn = et + GCOLS;
        if (etn < NT) {
            issue_b(sbU[(it & 1) ^ 1], etn * TN);
            cp_commit();
            cp_wait<1>();
        } else {
            cp_wait<0>();
        }
        __syncthreads();

        // Gate terms for this thread's 8 columns.
        float2 Cev[4];
        #pragma unroll
        for (int ni = 0; ni < 4; ni++)
            Cev[ni] = *(const float2*)&g_ce[bn + warpN * 32 + ni * 8 + 2 * (lane & 3)];

        int acc[4][4][4];
        #pragma unroll
        for (int mi = 0; mi < 4; mi++)
            #pragma unroll
            for (int ni = 0; ni < 4; ni++)
                #pragma unroll
                for (int r = 0; r < 4; r++) acc[mi][ni][r] = 0;

        #pragma unroll
        for (int ks = 0; ks < 2; ks++) {
            const int k0b = ks * 32;
            uint32_t af[4][4];
            #pragma unroll
            for (int mi = 0; mi < 4; mi++) ldsm_x4(af[mi], aAddr[mi] + k0b);
            uint32_t bf[4][2];
            #pragma unroll
            for (int ni = 0; ni < 4; ni++) ldsm_x2(bf[ni], cur + bOff[ni] + k0b);
            #pragma unroll
            for (int mi = 0; mi < 4; mi++)
                #pragma unroll
                for (int ni = 0; ni < 4; ni++)
                    mma_s8(acc[mi][ni], af[mi], bf[ni]);
        }

        // Hierarchical gate: per column (ni,parity), IMNMX-tree max of the 8
        // m-accumulators; conservative group test; detailed scan only if hit.
        #pragma unroll
        for (int ni = 0; ni < 4; ni++) {
            #pragma unroll
            for (int par = 0; par < 2; par++) {
                int imax = acc[0][ni][par];
                #pragma unroll
                for (int mi = 0; mi < 4; mi++) {
                    imax = max(imax, acc[mi][ni][par]);
                    imax = max(imax, acc[mi][ni][2 + par]);
                }
                float Cg = par ? Cev[ni].y : Cev[ni].x;
                float gbound = fmaf(__int2float_rn(imax), -inv128, rxmin + Cg);
                if (gbound < thrP) {
                    // rare: per-element exact-margin check + survivor push
                    #pragma unroll
                    for (int mi = 0; mi < 4; mi++) {
                        #pragma unroll
                        for (int half = 0; half < 2; half++) {
                            float d2a = fmaf(
                                __int2float_rn(acc[mi][ni][half * 2 + par]),
                                -inv128, Rxv[mi * 2 + half] + Cg);
                            if (d2a < thrP) {
                                int row = bm + warpM * 64 + mi * 16 +
                                          (lane >> 2) + half * 8;
                                int col = bn + warpN * 32 + ni * 8 +
                                          2 * (lane & 3) + par;
                                unsigned int q = atomicAdd(&g_nsurv, 1u);
                                if (q < MAXSURV)
                                    g_surv[q] = ((unsigned)row << 16) |
                                                (unsigned)col;
                            }
                        }
                    }
                }
            }
        }
        __syncthreads();   // all reads of cur done before it is re-prefetched
    }
}

// ---------------------------------------------------------------------------
// Survivors: exact fp32 recompute + exp + scatter-add; last block finalizes
// logits = GAMMA * log(class_sims + EPS).
// ---------------------------------------------------------------------------
__global__ void survivor_finalize_kernel(const float* __restrict__ x,
                                         const float* __restrict__ ex,
                                         const int* __restrict__ labels,
                                         float* __restrict__ out,
                                         int B, int NE, int nout) {
    unsigned int n = g_nsurv;
    if (n > MAXSURV) n = MAXSURV;
    const float beta = g_beta;
    for (unsigned int i = blockIdx.x * blockDim.x + threadIdx.x; i < n;
         i += gridDim.x * blockDim.x) {
        unsigned int p = g_surv[i];
        int row = (int)(p >> 16);
        int col = (int)(p & 0xFFFFu);
        if (row >= B || col >= NE) continue;
        const float* xr = x  + (size_t)row * DD;
        const float* er = ex + (size_t)col * DD;
        float s = 0.f;
        #pragma unroll
        for (int q = 0; q < DD / 4; q++) {
            float4 a = ((const float4*)xr)[q];
            float4 e = ((const float4*)er)[q];
            s += a.x*e.x + a.y*e.y + a.z*e.z + a.w*e.w;
        }
        float d2 = fmaxf(g_x2[row] + g_e2[col] - 2.f * s, 0.f);
        float bd = beta * d2;
        // skipped mass <= NE*exp(-60) << 1e-3 * EPS
        if (bd < 60.f)
            atomicAdd(&g_class[row * NUM_CLASSES + labels[col]], expf(-bd));
    }

    __shared__ unsigned int s_last;
    __threadfence();
    __syncthreads();
    if (threadIdx.x == 0)
        s_last = (atomicAdd(&g_done, 1u) == gridDim.x - 1) ? 1u : 0u;
    __syncthreads();
    if (s_last) {
        __threadfence();
        for (int i = threadIdx.x; i < nout; i += blockDim.x)
            out[i] = GAMMA * logf(g_class[i] + EPS);
    }
}

// ---------------------------------------------------------------------------
extern "C" void kernel_launch(void* const* d_in, const int* in_sizes, int n_in,
                              void* d_out, int out_size) {
    const float* x        = (const float*)d_in[0];
    const float* ex       = (const float*)d_in[1];
    const int*   labels   = (const int*)d_in[2];
    const float* beta_raw = (const float*)d_in[3];
    float* out = (float*)d_out;

    const int B  = in_sizes[0] / DD;
    const int NE = in_sizes[1] / DD;

    const int prep_blocks = (NE_PAD + MAXB) / 32;   // 1596
    prep_kernel<<<prep_blocks, 256>>>(x, ex, beta_raw, B, NE);

    dim3 grid(GCOLS, (B + TM - 1) / TM);            // 37 x 8
    exemplar_mma_kernel<<<grid, 256>>>(B, NE);

    survivor_finalize_kernel<<<148, 256>>>(x, ex, labels, out, B, NE, out_size);
}

// round 11
// speedup vs baseline: 1.3687x; 1.3687x over previous
#include <cuda_runtime.h>
#include <cuda_fp16.h>
#include <stdint.h>
#include <math.h>

// ---------------------------------------------------------------------------
// Problem constants
// ---------------------------------------------------------------------------
#define NUM_CLASSES 10
#define DD     64
#define MAXB   1024
#define NE_PAD 50048           // 391 tiles of 128
#define GAMMA  1.0f
#define EPS    1e-12f

// Tiling: fp16 HMMA (f16 accum) filter GEMM
#define TM 128
#define TN 128
#define GCOLS 37               // grid = 8 x 37 = 296 CTAs = 2/SM, one wave
#define ROWB 144               // smem row stride: 64 f16 + 8 pad

#define SM_A   0
#define SM_B0  (TM * ROWB)             // 18432
#define SM_B1  (SM_B0 + TN * ROWB)     // 36864
#define SM_TOT (SM_B1 + TN * ROWB)     // 55296 (dynamic smem)

#define MAXSURV (1u * 1024u * 1024u)

// ---------------------------------------------------------------------------
// Scratch (__device__ globals; no cudaMalloc allowed)
// ---------------------------------------------------------------------------
__device__ __half g_eh[(size_t)NE_PAD * DD];
__device__ __half g_xh[(size_t)MAXB * DD];
__device__ float g_e2[NE_PAD];
__device__ float g_x2[MAXB];
__device__ float g_class[MAXB * NUM_CLASSES];
__device__ float g_beta;
__device__ unsigned int g_nsurv;
__device__ unsigned int g_done;
__device__ unsigned int g_surv[MAXSURV];

// ---------------------------------------------------------------------------
// PTX helpers (baseline ISA only: ldmatrix, mma.sync f16, cp.async)
// ---------------------------------------------------------------------------
__device__ __forceinline__ uint32_t smem_to_u32(const void* p) {
    uint32_t a;
    asm("{ .reg .u64 t; cvta.to.shared.u64 t, %1; cvt.u32.u64 %0, t; }"
        : "=r"(a) : "l"(p));
    return a;
}
__device__ __forceinline__ void ldsm_x4(uint32_t* r, uint32_t addr) {
    asm volatile("ldmatrix.sync.aligned.m8n8.x4.shared.b16 {%0,%1,%2,%3}, [%4];"
                 : "=r"(r[0]), "=r"(r[1]), "=r"(r[2]), "=r"(r[3]) : "r"(addr));
}
__device__ __forceinline__ void ldsm_x2(uint32_t* r, uint32_t addr) {
    asm volatile("ldmatrix.sync.aligned.m8n8.x2.shared.b16 {%0,%1}, [%2];"
                 : "=r"(r[0]), "=r"(r[1]) : "r"(addr));
}
// f16 HMMA with f16 accumulators: D,C are 2 regs (4 halves packed).
__device__ __forceinline__ void mma_f16acc(uint32_t* c, const uint32_t* a,
                                           const uint32_t* b) {
    asm volatile(
        "mma.sync.aligned.m16n8k16.row.col.f16.f16.f16.f16 "
        "{%0,%1}, {%2,%3,%4,%5}, {%6,%7}, {%0,%1};"
        : "+r"(c[0]), "+r"(c[1])
        : "r"(a[0]), "r"(a[1]), "r"(a[2]), "r"(a[3]), "r"(b[0]), "r"(b[1]));
}
__device__ __forceinline__ void cp_async16(uint32_t dst, const void* src) {
    asm volatile("cp.async.cg.shared.global [%0], [%1], 16;"
                 :: "r"(dst), "l"(src) : "memory");
}
__device__ __forceinline__ void cp_commit() {
    asm volatile("cp.async.commit_group;" ::: "memory");
}
template <int N>
__device__ __forceinline__ void cp_wait() {
    asm volatile("cp.async.wait_group %0;" :: "n"(N) : "memory");
}
__device__ __forceinline__ uint32_t hmax2(uint32_t a, uint32_t b) {
    __half2 r = __hmax2(*(__half2*)&a, *(__half2*)&b);
    return *(uint32_t*)&r;
}

// ---------------------------------------------------------------------------
// Prep: fp16 conversion (padded), exact L2 norms, beta, zero bins.
// ---------------------------------------------------------------------------
__global__ void prep_kernel(const float* __restrict__ x,
                            const float* __restrict__ ex,
                            const float* __restrict__ beta_raw,
                            int B, int NE) {
    const int t = threadIdx.x;
    const int gid = blockIdx.x * 256 + t;
    if (gid < MAXB * NUM_CLASSES) g_class[gid] = 0.f;
    if (gid == 0) {
        float br = beta_raw[0];
        g_beta = (br > 20.f) ? br : log1pf(expf(br));
        g_nsurv = 0u;
        g_done  = 0u;
    }
    const int R = blockIdx.x * 32 + (t >> 3);   // padded row index
    const int part = t & 7;                      // 8-float segment
    bool is_x = false;
    int outr = R;
    const float* src = nullptr;
    if (R < NE_PAD) {
        if (R < NE) src = ex + (size_t)R * DD + part * 8;
    } else {
        int xr = R - NE_PAD;
        if (xr >= MAXB) return;
        is_x = true; outr = xr;
        if (xr < B) src = x + (size_t)xr * DD + part * 8;
    }
    float v[8];
    float s = 0.f;
    if (src) {
        #pragma unroll
        for (int q = 0; q < 2; q++) {
            float4 f = ((const float4*)src)[q];
            v[4*q+0] = f.x; v[4*q+1] = f.y; v[4*q+2] = f.z; v[4*q+3] = f.w;
            s += f.x*f.x + f.y*f.y + f.z*f.z + f.w*f.w;
        }
    } else {
        #pragma unroll
        for (int q = 0; q < 8; q++) v[q] = 0.f;
    }
    #pragma unroll
    for (int d = 1; d <= 4; d <<= 1)
        s += __shfl_xor_sync(0xFFFFFFFFu, s, d);
    alignas(16) __half hb[8];
    #pragma unroll
    for (int q = 0; q < 8; q++) hb[q] = __float2half_rn(v[q]);
    __half* dst = (is_x ? (g_xh + (size_t)outr * DD)
                        : (g_eh + (size_t)outr * DD)) + part * 8;
    *(uint4*)dst = *(uint4*)hb;
    if (part == 0) {
        if (is_x) g_x2[outr] = (outr < B) ? s : 0.f;
        else      g_e2[outr] = (outr < NE) ? s : 3.0e8f;  // padding never fires
    }
}

// ---------------------------------------------------------------------------
// Main: fp16 HMMA (f16 acc) filter GEMM, cp.async double-buffered B tiles.
// Packed hierarchical gate: per column pair, HMNMX2 tree over the 8
// (mi,half) accumulator pairs -> conservative compare -> rare detailed scan.
// Error bound: |d2_true - d2_f16| <= 0.7 < margin 1.0, so gating
// d2_f16 < 60/beta + 1 includes every true survivor.
// ---------------------------------------------------------------------------
__global__ void __launch_bounds__(256, 2)
exemplar_mma_kernel(int B, int NE) {
    extern __shared__ char smem[];
    const uint32_t saU = smem_to_u32(smem) + SM_A;
    const uint32_t sb0 = smem_to_u32(smem) + SM_B0;
    const uint32_t sb1 = smem_to_u32(smem) + SM_B1;

    const int t = threadIdx.x;
    const int wid = t >> 5, lane = t & 31;
    const int warpM = wid >> 2;            // 0..1
    const int warpN = wid & 3;             // 0..3
    const int bm = blockIdx.y * TM;
    const int NT = (NE + TN - 1) / TN;

    // Load A tile (128 rows x 64 f16) once.
    for (int i = t; i < TM * 8; i += 256) {
        int r = i >> 3, c = i & 7;
        *(uint4*)(smem + SM_A + r * ROWB + c * 16) =
            *(const uint4*)(g_xh + (size_t)(bm + r) * DD + c * 8);
    }

    // ldmatrix lane-address components
    const int rowA = (lane & 7) + ((lane >> 3) & 1) * 8;
    const int kA   = ((lane >> 4) & 1) * 8;
    const int l16  = lane & 15;
    const int rowBf = l16 & 7;
    const int kB    = ((l16 >> 3) & 1) * 8;

    uint32_t aAddr[4];
    #pragma unroll
    for (int mi = 0; mi < 4; mi++)
        aAddr[mi] = saU + (uint32_t)(warpM * 64 + mi * 16 + rowA) * ROWB + kA * 2;
    uint32_t bOff[4];
    #pragma unroll
    for (int ni = 0; ni < 4; ni++)
        bOff[ni] = (uint32_t)(warpN * 32 + ni * 8 + rowBf) * ROWB + kB * 2;

    const float beta = g_beta;
    const float thr  = 60.f / beta + 1.0f;  // margin covers f16 error (<=0.7)

    // x2 for this thread's 8 rows; xmin for the conservative group bound.
    float x2v[8];
    #pragma unroll
    for (int mi = 0; mi < 4; mi++) {
        int r0 = bm + warpM * 64 + mi * 16 + (lane >> 2);
        x2v[mi * 2 + 0] = g_x2[r0];
        x2v[mi * 2 + 1] = g_x2[r0 + 8];
    }
    float xmin = x2v[0];
    #pragma unroll
    for (int i = 1; i < 8; i++) xmin = fminf(xmin, x2v[i]);

    // cp.async B-tile issue: 4 x 16B per thread.
    const int pr = t >> 1;
    const int pc = (t & 1) * 2;
    auto issue_b = [&](uint32_t sbase, int bn) {
        const __half* src = g_eh + (size_t)(bn + pr) * DD;
        uint32_t drow = sbase + (uint32_t)pr * ROWB;
        cp_async16(drow + (pc + 0) * 16, src + (pc + 0) * 8);
        cp_async16(drow + (pc + 1) * 16, src + (pc + 1) * 8);
        cp_async16(drow + (pc + 4) * 16, src + (pc + 4) * 8);
        cp_async16(drow + (pc + 5) * 16, src + (pc + 5) * 8);
    };

    issue_b(sb0, blockIdx.x * TN);
    cp_commit();

    int it = 0;
    for (int et = blockIdx.x; et < NT; et += GCOLS, it++) {
        const int bn = et * TN;
        const uint32_t cur = (it & 1) ? sb1 : sb0;
        const uint32_t nxt = (it & 1) ? sb0 : sb1;
        const int etn = et + GCOLS;
        if (etn < NT) {
            issue_b(nxt, etn * TN);
            cp_commit();
            cp_wait<1>();
        } else {
            cp_wait<0>();
        }
        __syncthreads();

        float2 e2p[4];
        #pragma unroll
        for (int ni = 0; ni < 4; ni++)
            e2p[ni] = *(const float2*)&g_e2[bn + warpN * 32 + ni * 8 + 2 * (lane & 3)];

        uint32_t acc[4][4][2];   // f16x2 accumulators
        #pragma unroll
        for (int mi = 0; mi < 4; mi++)
            #pragma unroll
            for (int ni = 0; ni < 4; ni++) {
                acc[mi][ni][0] = 0u;
                acc[mi][ni][1] = 0u;
            }

        #pragma unroll
        for (int ks = 0; ks < 4; ks++) {
            const int k0b = ks * 32;
            uint32_t af[4][4];
            #pragma unroll
            for (int mi = 0; mi < 4; mi++) ldsm_x4(af[mi], aAddr[mi] + k0b);
            uint32_t bf[4][2];
            #pragma unroll
            for (int ni = 0; ni < 4; ni++) ldsm_x2(bf[ni], cur + bOff[ni] + k0b);
            #pragma unroll
            for (int mi = 0; mi < 4; mi++)
                #pragma unroll
                for (int ni = 0; ni < 4; ni++)
                    mma_f16acc(acc[mi][ni], af[mi], bf[ni]);
        }

        // Hierarchical gate per column pair (ni): packed max over 8 values.
        #pragma unroll
        for (int ni = 0; ni < 4; ni++) {
            uint32_t m01 = hmax2(acc[0][ni][0], acc[0][ni][1]);
            uint32_t m23 = hmax2(acc[1][ni][0], acc[1][ni][1]);
            uint32_t m45 = hmax2(acc[2][ni][0], acc[2][ni][1]);
            uint32_t m67 = hmax2(acc[3][ni][0], acc[3][ni][1]);
            uint32_t mm  = hmax2(hmax2(m01, m23), hmax2(m45, m67));
            float2 maxd = __half22float2(*(__half2*)&mm);
            // fire iff exists d2 = x2 + e2 - 2 dot < thr  (conservative: xmin)
            float cx = 0.5f * (xmin + e2p[ni].x - thr);
            float cy = 0.5f * (xmin + e2p[ni].y - thr);
            if (maxd.x > cx || maxd.y > cy) {
                // rare detailed scan of the 16 elements in this column pair
                #pragma unroll
                for (int mi = 0; mi < 4; mi++) {
                    #pragma unroll
                    for (int half = 0; half < 2; half++) {
                        float2 d = __half22float2(*(__half2*)&acc[mi][ni][half]);
                        float xv = x2v[mi * 2 + half];
                        #pragma unroll
                        for (int par = 0; par < 2; par++) {
                            float dot = par ? d.y : d.x;
                            float e2v = par ? e2p[ni].y : e2p[ni].x;
                            if (xv + e2v - 2.f * dot < thr) {
                                int row = bm + warpM * 64 + mi * 16 +
                                          (lane >> 2) + half * 8;
                                int col = bn + warpN * 32 + ni * 8 +
                                          2 * (lane & 3) + par;
                                unsigned int q = atomicAdd(&g_nsurv, 1u);
                                if (q < MAXSURV)
                                    g_surv[q] = ((unsigned)row << 16) |
                                                (unsigned)col;
                            }
                        }
                    }
                }
            }
        }
        __syncthreads();   // all reads of cur done before re-prefetch
    }
}

// ---------------------------------------------------------------------------
// Survivors: exact fp32 recompute + exp + scatter-add; last block finalizes
// logits = GAMMA * log(class_sims + EPS).
// ---------------------------------------------------------------------------
__global__ void survivor_finalize_kernel(const float* __restrict__ x,
                                         const float* __restrict__ ex,
                                         const int* __restrict__ labels,
                                         float* __restrict__ out,
                                         int B, int NE, int nout) {
    unsigned int n = g_nsurv;
    if (n > MAXSURV) n = MAXSURV;
    const float beta = g_beta;
    for (unsigned int i = blockIdx.x * blockDim.x + threadIdx.x; i < n;
         i += gridDim.x * blockDim.x) {
        unsigned int p = g_surv[i];
        int row = (int)(p >> 16);
        int col = (int)(p & 0xFFFFu);
        if (row >= B || col >= NE) continue;
        const float* xr = x  + (size_t)row * DD;
        const float* er = ex + (size_t)col * DD;
        float s = 0.f;
        #pragma unroll
        for (int q = 0; q < DD / 4; q++) {
            float4 a = ((const float4*)xr)[q];
            float4 e = ((const float4*)er)[q];
            s += a.x*e.x + a.y*e.y + a.z*e.z + a.w*e.w;
        }
        float d2 = fmaxf(g_x2[row] + g_e2[col] - 2.f * s, 0.f);
        float bd = beta * d2;
        // skipped mass <= NE*exp(-60) << 1e-3 * EPS
        if (bd < 60.f)
            atomicAdd(&g_class[row * NUM_CLASSES + labels[col]], expf(-bd));
    }

    __shared__ unsigned int s_last;
    __threadfence();
    __syncthreads();
    if (threadIdx.x == 0)
        s_last = (atomicAdd(&g_done, 1u) == gridDim.x - 1) ? 1u : 0u;
    __syncthreads();
    if (s_last) {
        __threadfence();
        for (int i = threadIdx.x; i < nout; i += blockDim.x)
            out[i] = GAMMA * logf(g_class[i] + EPS);
    }
}

// ---------------------------------------------------------------------------
extern "C" void kernel_launch(void* const* d_in, const int* in_sizes, int n_in,
                              void* d_out, int out_size) {
    const float* x        = (const float*)d_in[0];
    const float* ex       = (const float*)d_in[1];
    const int*   labels   = (const int*)d_in[2];
    const float* beta_raw = (const float*)d_in[3];
    float* out = (float*)d_out;

    const int B  = in_sizes[0] / DD;
    const int NE = in_sizes[1] / DD;

    const int prep_blocks = (NE_PAD + MAXB) / 32;   // 1596
    prep_kernel<<<prep_blocks, 256>>>(x, ex, beta_raw, B, NE);

    static int smem_set = 0;
    if (!smem_set) {
        cudaFuncSetAttribute(exemplar_mma_kernel,
                             cudaFuncAttributeMaxDynamicSharedMemorySize, SM_TOT);
        smem_set = 1;
    }
    dim3 grid(GCOLS, (B + TM - 1) / TM);            // 37 x 8
    exemplar_mma_kernel<<<grid, 256, SM_TOT>>>(B, NE);

    survivor_finalize_kernel<<<148, 256>>>(x, ex, labels, out, B, NE, out_size);
}